// round 15
// baseline (speedup 1.0000x reference)
#include <cuda_runtime.h>
#include <cuda_fp16.h>
#include <math.h>

#define N_USERS 100000
#define N_ITEMS 50000
#define N_NODES 150000
#define D       64
#define NNZ     2000000
#define BATCH   256
#define POPB    10
#define WL      0.25f   // 1/(N_LAYERS+1)

typedef unsigned long long u64t;
#define FULL 0xffffffffu
#define FLAG_AGG (1 << 30)
#define FLAG_PRE (2 << 30)
#define VMASK    ((1 << 30) - 1)

// ---------------- f32x2 packed-FMA helpers (sm_100+) -------------------------
__device__ __forceinline__ u64t pack2(float x, float y) {
    u64t r; asm("mov.b64 %0, {%1, %2};" : "=l"(r) : "f"(x), "f"(y)); return r;
}
__device__ __forceinline__ u64t pack1(float x) {
    u64t r; asm("mov.b64 %0, {%1, %1};" : "=l"(r) : "f"(x)); return r;
}
__device__ __forceinline__ void ffma2(u64t& d, u64t a, u64t b) {
    asm("fma.rn.f32x2 %0, %1, %2, %0;" : "+l"(d) : "l"(a), "l"(b));
}
__device__ __forceinline__ float2 unpack2(u64t v) {
    float2 f; asm("mov.b64 {%0, %1}, %2;" : "=f"(f.x), "=f"(f.y) : "l"(v)); return f;
}
__device__ __forceinline__ float2 h2f2(unsigned int h) {
    __half2 hh = *reinterpret_cast<__half2*>(&h);
    return __half22float2(hh);
}
__device__ __forceinline__ unsigned int f2h2(float x, float y) {
    __half2 hh = __floats2half2_rn(x, y);
    return *reinterpret_cast<unsigned int*>(&hh);
}

// ---------------- scratch (device globals) -----------------------------------
__device__ __align__(256) float  g_e1f[N_NODES * D];
__device__ __align__(256) float  g_e2f[N_NODES * D];   // also layer-1 input staging
__device__ __align__(256) float  g_outI[N_ITEMS * D];
__device__ __align__(256) __half g_Ih[(N_ITEMS + 32) * D];   // fp16 item factors (+pad)
__device__ __align__(256) __half g_Uh[BATCH * D];            // fp16 user factors
__device__ __align__(256) float  g_hp[POPB * D];       // pop_emb @ gW1[64:128]
__device__ __align__(256) float  g_qp[POPB * D];       // pop_emb @ iW1
__device__ int   g_rowptr[N_NODES + 1];
__device__ int   g_counts[N_NODES];                    // zero at entry (invariant)
__device__ int   g_bstate[256];                        // zero at entry (invariant)
__device__ int   g_rank[NNZ];
__device__ __align__(256) int2 g_csr[NNZ + 16];        // pad [NNZ..NNZ+16) stays 0

// ---------------- hist (capture rank) + stage fp32 embedding ------------------
__global__ void k_histinit(const float* __restrict__ ue, const float* __restrict__ ie,
                           const int* __restrict__ rows) {
    int t = blockIdx.x * blockDim.x + threadIdx.x;
    const int NU4 = N_USERS * D / 4;
    const int NT4 = N_NODES * D / 4;
    if (t < NT4) {
        float4 v = (t < NU4) ? ((const float4*)ue)[t] : ((const float4*)ie)[t - NU4];
        ((float4*)g_e2f)[t] = v;
    }
    if (t < NNZ) {
        int rk = atomicAdd(&g_counts[__ldg(&rows[t])], 1);
        g_rank[t] = rk;
    }
}

// ---------------- single-pass scan with decoupled lookback --------------------
__global__ void k_scan() {
    __shared__ int wsum[33];
    __shared__ int sprefix;
    int tid = threadIdx.x;
    int wid = tid >> 5, lane = tid & 31;
    int bid = blockIdx.x;
    int i = bid * 1024 + tid;
    int v = (i < N_NODES) ? g_counts[i] : 0;

    int sc = v;
#pragma unroll
    for (int off = 1; off < 32; off <<= 1) {
        int t = __shfl_up_sync(FULL, sc, off);
        if (lane >= off) sc += t;
    }
    if (lane == 31) wsum[wid] = sc;
    __syncthreads();
    if (wid == 0) {
        int s = wsum[lane];
#pragma unroll
        for (int off = 1; off < 32; off <<= 1) {
            int t = __shfl_up_sync(FULL, s, off);
            if (lane >= off) s += t;
        }
        wsum[lane + 1] = s;
        if (lane == 0) wsum[0] = 0;
    }
    __syncthreads();
    int total = wsum[32];

    if (tid == 0) {
        int val = (bid == 0) ? (FLAG_PRE | total) : (FLAG_AGG | total);
        __threadfence();
        atomicExch(&g_bstate[bid], val);
        if (bid == 0) sprefix = 0;
    }

    if (wid == 0 && bid > 0) {
        int ex = 0;
        int base = bid - 1;
        while (true) {
            int idx = base - lane;
            int s = 0;
            if (idx >= 0) {
                do { s = atomicAdd(&g_bstate[idx], 0); } while (s == 0);
            }
            unsigned pm = __ballot_sync(FULL, idx >= 0 && (s & FLAG_PRE));
            if (pm) {
                int firstp = __ffs(pm) - 1;
                int contrib = (idx >= 0 && lane <= firstp) ? (s & VMASK) : 0;
#pragma unroll
                for (int off = 16; off > 0; off >>= 1)
                    contrib += __shfl_down_sync(FULL, contrib, off);
                if (lane == 0) ex += contrib;
                break;
            } else {
                int contrib = (idx >= 0) ? (s & VMASK) : 0;
#pragma unroll
                for (int off = 16; off > 0; off >>= 1)
                    contrib += __shfl_down_sync(FULL, contrib, off);
                if (lane == 0) ex += contrib;
                base -= 32;
            }
        }
        if (lane == 0) {
            sprefix = ex;
            __threadfence();
            atomicExch(&g_bstate[bid], FLAG_PRE | ((ex + total) & VMASK));
        }
    }
    __syncthreads();

    if (i < N_NODES) g_rowptr[i] = sc - v + wsum[wid] + sprefix;
    if (i == 0) g_rowptr[N_NODES] = NNZ;
}

// rank-based scatter (NO atomics) + re-zero counts and block states ------------
__global__ void k_scatter(const float* __restrict__ vals,
                          const int* __restrict__ rows,
                          const int* __restrict__ cols) {
    int i = blockIdx.x * blockDim.x + threadIdx.x;
    if (i < N_NODES) g_counts[i] = 0;
    if (i < 256) g_bstate[i] = 0;
    if (i < NNZ) {
        int r  = __ldg(&rows[i]);
        int rk = g_rank[i];
        int pos = __ldg(&g_rowptr[r]) + rk;
        g_csr[pos] = make_int2(__ldg(&cols[i]), __float_as_int(__ldg(&vals[i])));
    }
}

// ---------------- SPMM (fp32 rows): 2 rows/warp, half-warp per row ------------
__global__ void k_spmm(const float4* __restrict__ ein, float4* __restrict__ eout) {
    int w    = (blockIdx.x * blockDim.x + threadIdx.x) >> 5;
    int lane = threadIdx.x & 31;
    int half = lane >> 4;
    int j    = lane & 15;
    int row  = 2 * w + half;
    if (row >= N_NODES) return;
    int s = __ldg(&g_rowptr[row]), e = __ldg(&g_rowptr[row + 1]);

    u64t a01 = 0ull, a23 = 0ull;
    for (int base = s; base < e; base += 8) {
        int2   c[8];
        float4 x[8];
        float  v[8];
#pragma unroll
        for (int k = 0; k < 8; k++) {
            int idx = base + k;
            c[k] = __ldg(&g_csr[idx]);                   // padded array: safe
            v[k] = (idx < e) ? __int_as_float(c[k].y) : 0.f;
        }
#pragma unroll
        for (int k = 0; k < 8; k++)
            x[k] = __ldg(ein + (size_t)c[k].x * 16 + j);
#pragma unroll
        for (int k = 0; k < 8; k++) {
            u64t vv = pack1(v[k]);
            ffma2(a01, vv, pack2(x[k].x, x[k].y));
            ffma2(a23, vv, pack2(x[k].z, x[k].w));
        }
    }
    float2 lo = unpack2(a01), hi = unpack2(a23);
    eout[(size_t)row * 16 + j] = make_float4(lo.x, lo.y, hi.x, hi.y);
}

// ---------------- layer-3 SPMM: 2 item rows/warp, fused out epilogue ----------
__global__ void k_spmm_items(const float* __restrict__ item_emb) {
    int w    = (blockIdx.x * blockDim.x + threadIdx.x) >> 5;
    int lane = threadIdx.x & 31;
    int half = lane >> 4;
    int j    = lane & 15;
    int it   = 2 * w + half;
    if (it >= N_ITEMS) return;
    int node = N_USERS + it;
    int s = __ldg(&g_rowptr[node]), e = __ldg(&g_rowptr[node + 1]);
    const float4* ein = (const float4*)g_e2f;

    u64t a01 = 0ull, a23 = 0ull;
    for (int base = s; base < e; base += 8) {
        int2   c[8];
        float4 x[8];
        float  v[8];
#pragma unroll
        for (int k = 0; k < 8; k++) {
            int idx = base + k;
            c[k] = __ldg(&g_csr[idx]);
            v[k] = (idx < e) ? __int_as_float(c[k].y) : 0.f;
        }
#pragma unroll
        for (int k = 0; k < 8; k++)
            x[k] = __ldg(ein + (size_t)c[k].x * 16 + j);
#pragma unroll
        for (int k = 0; k < 8; k++) {
            u64t vv = pack1(v[k]);
            ffma2(a01, vv, pack2(x[k].x, x[k].y));
            ffma2(a23, vv, pack2(x[k].z, x[k].w));
        }
    }
    float2 lo = unpack2(a01), hi = unpack2(a23);
    float4 e0 = __ldg((const float4*)(item_emb + (size_t)it * D) + j);
    float4 x1 = ((const float4*)g_e1f)[(size_t)node * 16 + j];
    float4 x2 = ((const float4*)g_e2f)[(size_t)node * 16 + j];
    ((float4*)(g_outI + (size_t)it * D))[j] = make_float4(
        WL * (e0.x + x1.x + x2.x + lo.x), WL * (e0.y + x1.y + x2.y + lo.y),
        WL * (e0.z + x1.z + x2.z + hi.x), WL * (e0.w + x1.w + x2.w + hi.y));
}

// ---------------- pop precompute + users MLP (merged; 64-thread blocks) --------
__global__ void k_pop_users(const float* __restrict__ pop_emb,
                            const float* __restrict__ gW1,
                            const float* __restrict__ iW1,
                            const int* __restrict__ users,
                            const float* __restrict__ user_emb,
                            const float* __restrict__ uW1, const float* __restrict__ ub1,
                            const float* __restrict__ uW2, const float* __restrict__ ub2) {
    if (blockIdx.x < POPB) {
        int b = blockIdx.x;
        int c = threadIdx.x;
        const float* pe = pop_emb + b * D;
        float hp = 0.f, qp = 0.f;
#pragma unroll 8
        for (int k = 0; k < 64; k++) {
            float x = __ldg(&pe[k]);
            hp += x * __ldg(&gW1[(64 + k) * 64 + c]);
            qp += x * __ldg(&iW1[k * 64 + c]);
        }
        g_hp[b * 64 + c] = hp;
        g_qp[b * 64 + c] = qp;
        return;
    }
    int w    = (blockIdx.x - POPB) * 2 + (threadIdx.x >> 5);
    int lane = threadIdx.x & 31;
    if (w >= BATCH) return;
    int u = __ldg(&users[w]);
    int s = __ldg(&g_rowptr[u]), e = __ldg(&g_rowptr[u + 1]);
    float ax = 0.f, ay = 0.f;
    const float2* e2f2 = (const float2*)g_e2f;
    for (int i = s; i < e; i++) {
        int2 c = __ldg(&g_csr[i]);
        float2 x = __ldg(&e2f2[(size_t)c.x * 32 + lane]);
        float v = __int_as_float(c.y);
        ax += v * x.x; ay += v * x.y;
    }
    float2 e0 = ((const float2*)(user_emb + (size_t)u * D))[lane];
    float2 x1 = ((const float2*)g_e1f)[(size_t)u * 32 + lane];
    float2 x2 = ((const float2*)g_e2f)[(size_t)u * 32 + lane];
    float xx = WL * (e0.x + x1.x + x2.x + ax);
    float xy = WL * (e0.y + x1.y + x2.y + ay);

    const float2* W1 = (const float2*)uW1;
    float hx = 0.f, hy = 0.f;
#pragma unroll 8
    for (int m = 0; m < 32; m++) {
        float2 wA = W1[(2 * m) * 32 + lane];
        float2 wB = W1[(2 * m + 1) * 32 + lane];
        float xA = __shfl_sync(FULL, xx, m);
        float xB = __shfl_sync(FULL, xy, m);
        hx += xA * wA.x + xB * wB.x;
        hy += xA * wA.y + xB * wB.y;
    }
    float2 b1 = ((const float2*)ub1)[lane];
    hx = fmaxf(hx + b1.x, 0.f);
    hy = fmaxf(hy + b1.y, 0.f);

    const float2* W2 = (const float2*)uW2;
    float yx = 0.f, yy = 0.f;
#pragma unroll 8
    for (int m = 0; m < 32; m++) {
        float2 wA = W2[(2 * m) * 32 + lane];
        float2 wB = W2[(2 * m + 1) * 32 + lane];
        float xA = __shfl_sync(FULL, hx, m);
        float xB = __shfl_sync(FULL, hy, m);
        yx += xA * wA.x + xB * wB.x;
        yy += xA * wA.y + xB * wB.y;
    }
    float2 b2 = ((const float2*)ub2)[lane];
    ((unsigned*)g_Uh)[w * 32 + lane] = f2h2(yx + b2.x, yy + b2.y);
}

// ---------------- items: fused dual-GEMM + gate + GEMM3 -> fp16 I -------------
__global__ __launch_bounds__(256) void k_items(
        const int* __restrict__ bins,
        const float* __restrict__ gW1, const float* __restrict__ gb1,
        const float* __restrict__ gW2, const float* __restrict__ gb2,
        const float* __restrict__ iW1, const float* __restrict__ ib1,
        const float* __restrict__ iW2, const float* __restrict__ ib2) {
    __shared__ float at[64][68];       // A^T (k, item); later Q^T
    __shared__ float shp[POPB][64];
    __shared__ float sqp[POPB][64];
    __shared__ int   sbin[64];
    int tid = threadIdx.x;
    int tx  = tid & 15;
    int ty  = tid >> 4;
    int it0 = blockIdx.x * 64;

    for (int idx = tid; idx < 64 * 64; idx += 256) {
        int item = idx >> 6, k = idx & 63;
        int it = it0 + item;
        at[k][item] = (it < N_ITEMS) ? g_outI[(size_t)it * D + k] : 0.f;
    }
    if (tid < 64) sbin[tid] = (it0 + tid < N_ITEMS) ? __ldg(&bins[it0 + tid]) : 0;
    for (int idx = tid; idx < POPB * 64; idx += 256) {
        shp[idx >> 6][idx & 63] = g_hp[idx];
        sqp[idx >> 6][idx & 63] = g_qp[idx];
    }
    __syncthreads();

    u64t h01[4] = {0,0,0,0}, h23[4] = {0,0,0,0};
    u64t p01[4] = {0,0,0,0}, p23[4] = {0,0,0,0};
#pragma unroll 4
    for (int k = 0; k < 64; k++) {
        float4 xa = *(const float4*)&at[k][ty * 4];
        float4 wg = __ldg((const float4*)&gW1[k * 64 + tx * 4]);
        float4 wi = __ldg((const float4*)&iW1[k * 64 + tx * 4]);
        u64t g01 = pack2(wg.x, wg.y), g23 = pack2(wg.z, wg.w);
        u64t i01 = pack2(wi.x, wi.y), i23 = pack2(wi.z, wi.w);
        u64t x0 = pack1(xa.x), x1 = pack1(xa.y), x2 = pack1(xa.z), x3 = pack1(xa.w);
        ffma2(h01[0], x0, g01); ffma2(h23[0], x0, g23);
        ffma2(p01[0], x0, i01); ffma2(p23[0], x0, i23);
        ffma2(h01[1], x1, g01); ffma2(h23[1], x1, g23);
        ffma2(p01[1], x1, i01); ffma2(p23[1], x1, i23);
        ffma2(h01[2], x2, g01); ffma2(h23[2], x2, g23);
        ffma2(p01[2], x2, i01); ffma2(p23[2], x2, i23);
        ffma2(h01[3], x3, g01); ffma2(h23[3], x3, g23);
        ffma2(p01[3], x3, i01); ffma2(p23[3], x3, i23);
    }

    float4 b1v = __ldg((const float4*)&gb1[tx * 4]);
    float4 w2v = __ldg((const float4*)&gW2[tx * 4]);
    float gb2v = __ldg(gb2);
    float z[4]; int binr[4];
#pragma unroll
    for (int r = 0; r < 4; r++) {
        binr[r] = sbin[ty * 4 + r];
        float4 hpv = *(const float4*)&shp[binr[r]][tx * 4];
        float2 hA = unpack2(h01[r]);
        float2 hB = unpack2(h23[r]);
        float t = fmaxf(hA.x + hpv.x + b1v.x, 0.f) * w2v.x
                + fmaxf(hA.y + hpv.y + b1v.y, 0.f) * w2v.y
                + fmaxf(hB.x + hpv.z + b1v.z, 0.f) * w2v.z
                + fmaxf(hB.y + hpv.w + b1v.w, 0.f) * w2v.w;
#pragma unroll
        for (int off = 8; off > 0; off >>= 1) t += __shfl_xor_sync(FULL, t, off);
        z[r] = 1.f / (1.f + expf(-(t + gb2v)));
    }

    float4 biv = __ldg((const float4*)&ib1[tx * 4]);
    float qv[4][4];
#pragma unroll
    for (int r = 0; r < 4; r++) {
        float4 qpv = *(const float4*)&sqp[binr[r]][tx * 4];
        float2 qA = unpack2(p01[r]);
        float2 qB = unpack2(p23[r]);
        float zi = z[r], zo = 1.f - z[r];
        qv[r][0] = fmaxf(zo * qA.x + zi * qpv.x + biv.x, 0.f);
        qv[r][1] = fmaxf(zo * qA.y + zi * qpv.y + biv.y, 0.f);
        qv[r][2] = fmaxf(zo * qB.x + zi * qpv.z + biv.z, 0.f);
        qv[r][3] = fmaxf(zo * qB.y + zi * qpv.w + biv.w, 0.f);
    }
    __syncthreads();
#pragma unroll
    for (int cc = 0; cc < 4; cc++)
        *(float4*)&at[tx * 4 + cc][ty * 4] =
            make_float4(qv[0][cc], qv[1][cc], qv[2][cc], qv[3][cc]);
    __syncthreads();

    u64t y01[4] = {0,0,0,0}, y23[4] = {0,0,0,0};
#pragma unroll 8
    for (int k = 0; k < 64; k++) {
        float4 xa = *(const float4*)&at[k][ty * 4];
        float4 w  = __ldg((const float4*)&iW2[k * 64 + tx * 4]);
        u64t w01 = pack2(w.x, w.y), w23 = pack2(w.z, w.w);
        u64t x0 = pack1(xa.x), x1 = pack1(xa.y), x2 = pack1(xa.z), x3 = pack1(xa.w);
        ffma2(y01[0], x0, w01); ffma2(y23[0], x0, w23);
        ffma2(y01[1], x1, w01); ffma2(y23[1], x1, w23);
        ffma2(y01[2], x2, w01); ffma2(y23[2], x2, w23);
        ffma2(y01[3], x3, w01); ffma2(y23[3], x3, w23);
    }
    float4 bo = __ldg((const float4*)&ib2[tx * 4]);
#pragma unroll
    for (int r = 0; r < 4; r++) {
        int item = it0 + ty * 4 + r;
        if (item < N_ITEMS) {
            float2 yA = unpack2(y01[r]);
            float2 yB = unpack2(y23[r]);
            ((uint2*)(g_Ih + (size_t)item * D))[tx] =
                make_uint2(f2h2(yA.x + bo.x, yA.y + bo.y),
                           f2h2(yB.x + bo.z, yB.y + bo.w));
        }
    }
}

// ---------------- scores: fp16 tensor-core GEMM (mma.sync m16n8k16) -----------
__global__ __launch_bounds__(256) void k_scores(
        const float* __restrict__ user_bias,
        const float* __restrict__ item_bias,
        const int* __restrict__ users,
        float* __restrict__ out) {
    int lane = threadIdx.x & 31;
    int warp = threadIdx.x >> 5;      // 0..7
    int g = lane >> 2, t = lane & 3;
    int n0 = blockIdx.x * 32;
    int m0 = warp * 32;

    float c[2][4][4] = {};
#pragma unroll
    for (int ks = 0; ks < 4; ks++) {
        unsigned a[2][4], b[4][2];
#pragma unroll
        for (int mt = 0; mt < 2; mt++) {
            const __half* base = g_Uh + (m0 + mt * 16 + g) * D + ks * 16 + 2 * t;
            a[mt][0] = *(const unsigned*)(base);
            a[mt][1] = *(const unsigned*)(base + 8 * D);
            a[mt][2] = *(const unsigned*)(base + 8);
            a[mt][3] = *(const unsigned*)(base + 8 * D + 8);
        }
#pragma unroll
        for (int nt = 0; nt < 4; nt++) {
            const __half* bb = g_Ih + (size_t)(n0 + nt * 8 + g) * D + ks * 16 + 2 * t;
            b[nt][0] = *(const unsigned*)(bb);
            b[nt][1] = *(const unsigned*)(bb + 8);
        }
#pragma unroll
        for (int mt = 0; mt < 2; mt++)
#pragma unroll
            for (int nt = 0; nt < 4; nt++)
                asm volatile(
                    "mma.sync.aligned.m16n8k16.row.col.f32.f16.f16.f32 "
                    "{%0,%1,%2,%3}, {%4,%5,%6,%7}, {%8,%9}, {%0,%1,%2,%3};"
                    : "+f"(c[mt][nt][0]), "+f"(c[mt][nt][1]),
                      "+f"(c[mt][nt][2]), "+f"(c[mt][nt][3])
                    : "r"(a[mt][0]), "r"(a[mt][1]), "r"(a[mt][2]), "r"(a[mt][3]),
                      "r"(b[nt][0]), "r"(b[nt][1]));
    }

#pragma unroll
    for (int mt = 0; mt < 2; mt++) {
        int m = m0 + mt * 16 + g;
        float ub0 = __ldg(&user_bias[__ldg(&users[m])]);
        float ub8 = __ldg(&user_bias[__ldg(&users[m + 8])]);
#pragma unroll
        for (int nt = 0; nt < 4; nt++) {
            int n = n0 + nt * 8 + 2 * t;
            if (n < N_ITEMS) {
                float2 ib = *(const float2*)&item_bias[n];
                float2 r0 = make_float2(c[mt][nt][0] + ub0 + ib.x,
                                        c[mt][nt][1] + ub0 + ib.y);
                float2 r1 = make_float2(c[mt][nt][2] + ub8 + ib.x,
                                        c[mt][nt][3] + ub8 + ib.y);
                __stcs((float2*)&out[(size_t)m * N_ITEMS + n], r0);
                __stcs((float2*)&out[(size_t)(m + 8) * N_ITEMS + n], r1);
            }
        }
    }
}

// ---------------- launch -------------------------------------------------------
extern "C" void kernel_launch(void* const* d_in, const int* in_sizes, int n_in,
                              void* d_out, int out_size) {
    const float* user_emb  = (const float*)d_in[0];
    const float* item_emb  = (const float*)d_in[1];
    const float* user_bias = (const float*)d_in[2];
    const float* item_bias = (const float*)d_in[3];
    const float* pop_emb   = (const float*)d_in[4];
    const float* uW1 = (const float*)d_in[5];
    const float* ub1 = (const float*)d_in[6];
    const float* uW2 = (const float*)d_in[7];
    const float* ub2 = (const float*)d_in[8];
    const float* iW1 = (const float*)d_in[9];
    const float* ib1 = (const float*)d_in[10];
    const float* iW2 = (const float*)d_in[11];
    const float* ib2 = (const float*)d_in[12];
    const float* gW1 = (const float*)d_in[13];
    const float* gb1 = (const float*)d_in[14];
    const float* gW2 = (const float*)d_in[15];
    const float* gb2 = (const float*)d_in[16];
    const float* adj_vals = (const float*)d_in[17];
    const int*   adj_rows = (const int*)d_in[18];
    const int*   adj_cols = (const int*)d_in[19];
    const int*   bins     = (const int*)d_in[20];
    const int*   users    = (const int*)d_in[21];
    float* out = (float*)d_out;

    float4* e1f; cudaGetSymbolAddress((void**)&e1f, g_e1f);
    float4* e2f; cudaGetSymbolAddress((void**)&e2f, g_e2f);

    // 1: hist (rank capture) + stage fp32 embeddings
    const int NT4 = N_NODES * D / 4;
    k_histinit<<<(NT4 + 255) / 256, 256>>>(user_emb, item_emb, adj_rows);
    // 2: single-pass decoupled-lookback scan
    int nb = (N_NODES + 1023) / 1024;
    k_scan<<<nb, 1024>>>();
    // 3: rank-based scatter (atomic-free; re-zeroes counts + bstate)
    k_scatter<<<(NNZ + 255) / 256, 256>>>(adj_vals, adj_rows, adj_cols);

    // 4: layer 1 (PROFILED slot) — 2 rows per warp, fp32 gathers
    int spmmBlocks = (N_NODES / 2 * 32 + 255) / 256;   // 9375
    k_spmm<<<spmmBlocks, 256>>>(e2f, e1f);
    // 5: layer 2
    k_spmm<<<spmmBlocks, 256>>>(e1f, e2f);
    // 6: layer 3 (items) + epilogue — 2 items per warp
    int itemBlocks = (N_ITEMS / 2 * 32 + 255) / 256;   // 3125
    k_spmm_items<<<itemBlocks, 256>>>(item_emb);

    // 7: pop precompute + users MLP (merged)
    k_pop_users<<<POPB + BATCH / 2, 64>>>(pop_emb, gW1, iW1,
                                          users, user_emb, uW1, ub1, uW2, ub2);
    // 8: items MLP chain
    k_items<<<(N_ITEMS + 63) / 64, 256>>>(bins, gW1, gb1, gW2, gb2,
                                          iW1, ib1, iW2, ib2);

    // 9: scores (tensor cores)
    k_scores<<<(N_ITEMS + 31) / 32, 256>>>(user_bias, item_bias, users, out);
}

// round 16
// speedup vs baseline: 1.1382x; 1.1382x over previous
#include <cuda_runtime.h>
#include <cuda_fp16.h>
#include <math.h>

#define N_USERS 100000
#define N_ITEMS 50000
#define N_NODES 150000
#define D       64
#define NNZ     2000000
#define BATCH   256
#define POPB    10
#define WL      0.25f   // 1/(N_LAYERS+1)

typedef unsigned long long u64t;
#define FULL 0xffffffffu
#define FLAG_AGG (1 << 30)
#define FLAG_PRE (2 << 30)
#define VMASK    ((1 << 30) - 1)

// ---------------- f32x2 packed-FMA helpers (sm_100+) -------------------------
__device__ __forceinline__ u64t pack2(float x, float y) {
    u64t r; asm("mov.b64 %0, {%1, %2};" : "=l"(r) : "f"(x), "f"(y)); return r;
}
__device__ __forceinline__ u64t pack1(float x) {
    u64t r; asm("mov.b64 %0, {%1, %1};" : "=l"(r) : "f"(x)); return r;
}
__device__ __forceinline__ void ffma2(u64t& d, u64t a, u64t b) {
    asm("fma.rn.f32x2 %0, %1, %2, %0;" : "+l"(d) : "l"(a), "l"(b));
}
__device__ __forceinline__ float2 unpack2(u64t v) {
    float2 f; asm("mov.b64 {%0, %1}, %2;" : "=f"(f.x), "=f"(f.y) : "l"(v)); return f;
}
__device__ __forceinline__ float2 h2f2(unsigned int h) {
    __half2 hh = *reinterpret_cast<__half2*>(&h);
    return __half22float2(hh);
}
__device__ __forceinline__ unsigned int f2h2(float x, float y) {
    __half2 hh = __floats2half2_rn(x, y);
    return *reinterpret_cast<unsigned int*>(&hh);
}

// ---------------- scratch (device globals) -----------------------------------
__device__ __align__(256) __half g_e1h[N_NODES * D];
__device__ __align__(256) __half g_e2h[N_NODES * D];   // also layer-1 input staging
__device__ __align__(256) __half g_Ih[(N_ITEMS + 32) * D];   // fp16 item factors (+pad)
__device__ __align__(256) __half g_Uh[BATCH * D];            // fp16 user factors
__device__ __align__(256) float  g_hp[POPB * D];       // pop_emb @ gW1[64:128]
__device__ __align__(256) float  g_qp[POPB * D];       // pop_emb @ iW1
__device__ int   g_rowptr[N_NODES + 1];
__device__ int   g_counts[N_NODES];                    // zero at entry (invariant)
__device__ int   g_bstate[256];                        // zero at entry (invariant)
__device__ int   g_rank[NNZ];
__device__ __align__(256) int2 g_csr[NNZ + 16];        // pad [NNZ..NNZ+16) stays 0

// ---------------- hist (capture rank) + stage fp16 embedding ------------------
__global__ void k_histinit(const float* __restrict__ ue, const float* __restrict__ ie,
                           const int* __restrict__ rows) {
    int t = blockIdx.x * blockDim.x + threadIdx.x;
    const int NU4 = N_USERS * D / 4;
    const int NT4 = N_NODES * D / 4;
    if (t < NT4) {
        float4 v = (t < NU4) ? ((const float4*)ue)[t] : ((const float4*)ie)[t - NU4];
        ((uint2*)g_e2h)[t] = make_uint2(f2h2(v.x, v.y), f2h2(v.z, v.w));
    }
    if (t < NNZ) {
        int rk = atomicAdd(&g_counts[__ldg(&rows[t])], 1);
        g_rank[t] = rk;
    }
}

// ---------------- single-pass scan with decoupled lookback --------------------
__global__ void k_scan() {
    __shared__ int wsum[33];
    __shared__ int sprefix;
    int tid = threadIdx.x;
    int wid = tid >> 5, lane = tid & 31;
    int bid = blockIdx.x;
    int i = bid * 1024 + tid;
    int v = (i < N_NODES) ? g_counts[i] : 0;

    int sc = v;
#pragma unroll
    for (int off = 1; off < 32; off <<= 1) {
        int t = __shfl_up_sync(FULL, sc, off);
        if (lane >= off) sc += t;
    }
    if (lane == 31) wsum[wid] = sc;
    __syncthreads();
    if (wid == 0) {
        int s = wsum[lane];
#pragma unroll
        for (int off = 1; off < 32; off <<= 1) {
            int t = __shfl_up_sync(FULL, s, off);
            if (lane >= off) s += t;
        }
        wsum[lane + 1] = s;
        if (lane == 0) wsum[0] = 0;
    }
    __syncthreads();
    int total = wsum[32];

    if (tid == 0) {
        int val = (bid == 0) ? (FLAG_PRE | total) : (FLAG_AGG | total);
        __threadfence();
        atomicExch(&g_bstate[bid], val);
        if (bid == 0) sprefix = 0;
    }

    if (wid == 0 && bid > 0) {
        int ex = 0;
        int base = bid - 1;
        while (true) {
            int idx = base - lane;
            int s = 0;
            if (idx >= 0) {
                do { s = atomicAdd(&g_bstate[idx], 0); } while (s == 0);
            }
            unsigned pm = __ballot_sync(FULL, idx >= 0 && (s & FLAG_PRE));
            if (pm) {
                int firstp = __ffs(pm) - 1;
                int contrib = (idx >= 0 && lane <= firstp) ? (s & VMASK) : 0;
#pragma unroll
                for (int off = 16; off > 0; off >>= 1)
                    contrib += __shfl_down_sync(FULL, contrib, off);
                if (lane == 0) ex += contrib;
                break;
            } else {
                int contrib = (idx >= 0) ? (s & VMASK) : 0;
#pragma unroll
                for (int off = 16; off > 0; off >>= 1)
                    contrib += __shfl_down_sync(FULL, contrib, off);
                if (lane == 0) ex += contrib;
                base -= 32;
            }
        }
        if (lane == 0) {
            sprefix = ex;
            __threadfence();
            atomicExch(&g_bstate[bid], FLAG_PRE | ((ex + total) & VMASK));
        }
    }
    __syncthreads();

    if (i < N_NODES) g_rowptr[i] = sc - v + wsum[wid] + sprefix;
    if (i == 0) g_rowptr[N_NODES] = NNZ;
}

// rank-based scatter (NO atomics) + re-zero counts and block states ------------
__global__ void k_scatter(const float* __restrict__ vals,
                          const int* __restrict__ rows,
                          const int* __restrict__ cols) {
    int i = blockIdx.x * blockDim.x + threadIdx.x;
    if (i < N_NODES) g_counts[i] = 0;
    if (i < 256) g_bstate[i] = 0;
    if (i < NNZ) {
        int r  = __ldg(&rows[i]);
        int rk = g_rank[i];
        int pos = __ldg(&g_rowptr[r]) + rk;
        g_csr[pos] = make_int2(__ldg(&cols[i]), __float_as_int(__ldg(&vals[i])));
    }
}

// ---------------- SPMM (fp16 rows): 2 rows/warp, half-warp per row ------------
__global__ void k_spmm(const uint2* __restrict__ ein, uint2* __restrict__ eout) {
    int w    = (blockIdx.x * blockDim.x + threadIdx.x) >> 5;
    int lane = threadIdx.x & 31;
    int half = lane >> 4;
    int j    = lane & 15;
    int row  = 2 * w + half;
    if (row >= N_NODES) return;
    int s = __ldg(&g_rowptr[row]), e = __ldg(&g_rowptr[row + 1]);

    u64t a01 = 0ull, a23 = 0ull;
    for (int base = s; base < e; base += 8) {
        int2  c[8];
        uint2 x[8];
        float v[8];
#pragma unroll
        for (int k = 0; k < 8; k++) {
            int idx = base + k;
            c[k] = __ldg(&g_csr[idx]);                   // padded array: safe
            v[k] = (idx < e) ? __int_as_float(c[k].y) : 0.f;
        }
#pragma unroll
        for (int k = 0; k < 8; k++)
            x[k] = __ldg(ein + (size_t)c[k].x * 16 + j);
#pragma unroll
        for (int k = 0; k < 8; k++) {
            u64t vv = pack1(v[k]);
            float2 f;
            f = h2f2(x[k].x); ffma2(a01, vv, pack2(f.x, f.y));
            f = h2f2(x[k].y); ffma2(a23, vv, pack2(f.x, f.y));
        }
    }
    float2 lo = unpack2(a01), hi = unpack2(a23);
    eout[(size_t)row * 16 + j] = make_uint2(f2h2(lo.x, lo.y), f2h2(hi.x, hi.y));
}

// ---------------- pop precompute + users MLP (merged; 64-thread blocks) --------
__global__ void k_pop_users(const float* __restrict__ pop_emb,
                            const float* __restrict__ gW1,
                            const float* __restrict__ iW1,
                            const int* __restrict__ users,
                            const float* __restrict__ user_emb,
                            const float* __restrict__ uW1, const float* __restrict__ ub1,
                            const float* __restrict__ uW2, const float* __restrict__ ub2) {
    if (blockIdx.x < POPB) {
        int b = blockIdx.x;
        int c = threadIdx.x;
        const float* pe = pop_emb + b * D;
        float hp = 0.f, qp = 0.f;
#pragma unroll 8
        for (int k = 0; k < 64; k++) {
            float x = __ldg(&pe[k]);
            hp += x * __ldg(&gW1[(64 + k) * 64 + c]);
            qp += x * __ldg(&iW1[k * 64 + c]);
        }
        g_hp[b * 64 + c] = hp;
        g_qp[b * 64 + c] = qp;
        return;
    }
    int w    = (blockIdx.x - POPB) * 2 + (threadIdx.x >> 5);
    int lane = threadIdx.x & 31;
    if (w >= BATCH) return;
    int u = __ldg(&users[w]);
    int s = __ldg(&g_rowptr[u]), e = __ldg(&g_rowptr[u + 1]);
    float ax = 0.f, ay = 0.f;
    const __half2* e2h2 = (const __half2*)g_e2h;
    for (int i = s; i < e; i++) {
        int2 c = __ldg(&g_csr[i]);
        float2 x = __half22float2(__ldg(&e2h2[(size_t)c.x * 32 + lane]));
        float v = __int_as_float(c.y);
        ax += v * x.x; ay += v * x.y;
    }
    float2 e0 = ((const float2*)(user_emb + (size_t)u * D))[lane];
    float2 x1 = __half22float2(((const __half2*)g_e1h)[(size_t)u * 32 + lane]);
    float2 x2 = __half22float2(((const __half2*)g_e2h)[(size_t)u * 32 + lane]);
    float xx = WL * (e0.x + x1.x + x2.x + ax);
    float xy = WL * (e0.y + x1.y + x2.y + ay);

    const float2* W1 = (const float2*)uW1;
    float hx = 0.f, hy = 0.f;
#pragma unroll 8
    for (int m = 0; m < 32; m++) {
        float2 wA = W1[(2 * m) * 32 + lane];
        float2 wB = W1[(2 * m + 1) * 32 + lane];
        float xA = __shfl_sync(FULL, xx, m);
        float xB = __shfl_sync(FULL, xy, m);
        hx += xA * wA.x + xB * wB.x;
        hy += xA * wA.y + xB * wB.y;
    }
    float2 b1 = ((const float2*)ub1)[lane];
    hx = fmaxf(hx + b1.x, 0.f);
    hy = fmaxf(hy + b1.y, 0.f);

    const float2* W2 = (const float2*)uW2;
    float yx = 0.f, yy = 0.f;
#pragma unroll 8
    for (int m = 0; m < 32; m++) {
        float2 wA = W2[(2 * m) * 32 + lane];
        float2 wB = W2[(2 * m + 1) * 32 + lane];
        float xA = __shfl_sync(FULL, hx, m);
        float xB = __shfl_sync(FULL, hy, m);
        yx += xA * wA.x + xB * wB.x;
        yy += xA * wA.y + xB * wB.y;
    }
    float2 b2 = ((const float2*)ub2)[lane];
    ((unsigned*)g_Uh)[w * 32 + lane] = f2h2(yx + b2.x, yy + b2.y);
}

// ---------------- items: FUSED layer-3 SPMM + gate + GEMM chain -> fp16 I -----
__global__ __launch_bounds__(256) void k_items(
        const float* __restrict__ item_emb,
        const int* __restrict__ bins,
        const float* __restrict__ gW1, const float* __restrict__ gb1,
        const float* __restrict__ gW2, const float* __restrict__ gb2,
        const float* __restrict__ iW1, const float* __restrict__ ib1,
        const float* __restrict__ iW2, const float* __restrict__ ib2) {
    __shared__ float at[64][68];       // A^T (k, item); later Q^T
    __shared__ float shp[POPB][64];
    __shared__ float sqp[POPB][64];
    __shared__ int   sbin[64];
    int tid  = threadIdx.x;
    int warp = tid >> 5;
    int lane = tid & 31;
    int tx   = tid & 15;
    int ty   = tid >> 4;
    int it0  = blockIdx.x * 64;

    // ---- phase 0: layer-3 SPMM for this block's 64 items, direct to smem ----
    {
        int half = lane >> 4;
        int j    = lane & 15;
        const uint2* ein = (const uint2*)g_e2h;
#pragma unroll
        for (int p = 0; p < 4; p++) {
            int local = warp * 8 + 2 * p + half;      // 0..63
            int it = it0 + local;
            float4 r = make_float4(0.f, 0.f, 0.f, 0.f);
            if (it < N_ITEMS) {
                int node = N_USERS + it;
                int s = __ldg(&g_rowptr[node]), e = __ldg(&g_rowptr[node + 1]);
                u64t a01 = 0ull, a23 = 0ull;
                for (int base = s; base < e; base += 8) {
                    int2  c[8];
                    uint2 x[8];
                    float v[8];
#pragma unroll
                    for (int k = 0; k < 8; k++) {
                        int idx = base + k;
                        c[k] = __ldg(&g_csr[idx]);
                        v[k] = (idx < e) ? __int_as_float(c[k].y) : 0.f;
                    }
#pragma unroll
                    for (int k = 0; k < 8; k++)
                        x[k] = __ldg(ein + (size_t)c[k].x * 16 + j);
#pragma unroll
                    for (int k = 0; k < 8; k++) {
                        u64t vv = pack1(v[k]);
                        float2 f;
                        f = h2f2(x[k].x); ffma2(a01, vv, pack2(f.x, f.y));
                        f = h2f2(x[k].y); ffma2(a23, vv, pack2(f.x, f.y));
                    }
                }
                float2 lo = unpack2(a01), hi = unpack2(a23);
                float4 e0 = __ldg((const float4*)(item_emb + (size_t)it * D) + j);
                uint2 h1 = ((const uint2*)g_e1h)[(size_t)node * 16 + j];
                uint2 h2 = ((const uint2*)g_e2h)[(size_t)node * 16 + j];
                float2 x1a = h2f2(h1.x), x1b = h2f2(h1.y);
                float2 x2a = h2f2(h2.x), x2b = h2f2(h2.y);
                r = make_float4(
                    WL * (e0.x + x1a.x + x2a.x + lo.x),
                    WL * (e0.y + x1a.y + x2a.y + lo.y),
                    WL * (e0.z + x1b.x + x2b.x + hi.x),
                    WL * (e0.w + x1b.y + x2b.y + hi.y));
            }
            at[4 * j + 0][local] = r.x;
            at[4 * j + 1][local] = r.y;
            at[4 * j + 2][local] = r.z;
            at[4 * j + 3][local] = r.w;
        }
    }
    if (tid < 64) sbin[tid] = (it0 + tid < N_ITEMS) ? __ldg(&bins[it0 + tid]) : 0;
    for (int idx = tid; idx < POPB * 64; idx += 256) {
        shp[idx >> 6][idx & 63] = g_hp[idx];
        sqp[idx >> 6][idx & 63] = g_qp[idx];
    }
    __syncthreads();

    // ---- phase 1: fused dual-GEMM (gate hidden + item-MLP pre) ----
    u64t h01[4] = {0,0,0,0}, h23[4] = {0,0,0,0};
    u64t p01[4] = {0,0,0,0}, p23[4] = {0,0,0,0};
#pragma unroll 4
    for (int k = 0; k < 64; k++) {
        float4 xa = *(const float4*)&at[k][ty * 4];
        float4 wg = __ldg((const float4*)&gW1[k * 64 + tx * 4]);
        float4 wi = __ldg((const float4*)&iW1[k * 64 + tx * 4]);
        u64t g01 = pack2(wg.x, wg.y), g23 = pack2(wg.z, wg.w);
        u64t i01 = pack2(wi.x, wi.y), i23 = pack2(wi.z, wi.w);
        u64t x0 = pack1(xa.x), x1 = pack1(xa.y), x2 = pack1(xa.z), x3 = pack1(xa.w);
        ffma2(h01[0], x0, g01); ffma2(h23[0], x0, g23);
        ffma2(p01[0], x0, i01); ffma2(p23[0], x0, i23);
        ffma2(h01[1], x1, g01); ffma2(h23[1], x1, g23);
        ffma2(p01[1], x1, i01); ffma2(p23[1], x1, i23);
        ffma2(h01[2], x2, g01); ffma2(h23[2], x2, g23);
        ffma2(p01[2], x2, i01); ffma2(p23[2], x2, i23);
        ffma2(h01[3], x3, g01); ffma2(h23[3], x3, g23);
        ffma2(p01[3], x3, i01); ffma2(p23[3], x3, i23);
    }

    float4 b1v = __ldg((const float4*)&gb1[tx * 4]);
    float4 w2v = __ldg((const float4*)&gW2[tx * 4]);
    float gb2v = __ldg(gb2);
    float z[4]; int binr[4];
#pragma unroll
    for (int r = 0; r < 4; r++) {
        binr[r] = sbin[ty * 4 + r];
        float4 hpv = *(const float4*)&shp[binr[r]][tx * 4];
        float2 hA = unpack2(h01[r]);
        float2 hB = unpack2(h23[r]);
        float t = fmaxf(hA.x + hpv.x + b1v.x, 0.f) * w2v.x
                + fmaxf(hA.y + hpv.y + b1v.y, 0.f) * w2v.y
                + fmaxf(hB.x + hpv.z + b1v.z, 0.f) * w2v.z
                + fmaxf(hB.y + hpv.w + b1v.w, 0.f) * w2v.w;
#pragma unroll
        for (int off = 8; off > 0; off >>= 1) t += __shfl_xor_sync(FULL, t, off);
        z[r] = 1.f / (1.f + expf(-(t + gb2v)));
    }

    float4 biv = __ldg((const float4*)&ib1[tx * 4]);
    float qv[4][4];
#pragma unroll
    for (int r = 0; r < 4; r++) {
        float4 qpv = *(const float4*)&sqp[binr[r]][tx * 4];
        float2 qA = unpack2(p01[r]);
        float2 qB = unpack2(p23[r]);
        float zi = z[r], zo = 1.f - z[r];
        qv[r][0] = fmaxf(zo * qA.x + zi * qpv.x + biv.x, 0.f);
        qv[r][1] = fmaxf(zo * qA.y + zi * qpv.y + biv.y, 0.f);
        qv[r][2] = fmaxf(zo * qB.x + zi * qpv.z + biv.z, 0.f);
        qv[r][3] = fmaxf(zo * qB.y + zi * qpv.w + biv.w, 0.f);
    }
    __syncthreads();
#pragma unroll
    for (int cc = 0; cc < 4; cc++)
        *(float4*)&at[tx * 4 + cc][ty * 4] =
            make_float4(qv[0][cc], qv[1][cc], qv[2][cc], qv[3][cc]);
    __syncthreads();

    u64t y01[4] = {0,0,0,0}, y23[4] = {0,0,0,0};
#pragma unroll 8
    for (int k = 0; k < 64; k++) {
        float4 xa = *(const float4*)&at[k][ty * 4];
        float4 w  = __ldg((const float4*)&iW2[k * 64 + tx * 4]);
        u64t w01 = pack2(w.x, w.y), w23 = pack2(w.z, w.w);
        u64t x0 = pack1(xa.x), x1 = pack1(xa.y), x2 = pack1(xa.z), x3 = pack1(xa.w);
        ffma2(y01[0], x0, w01); ffma2(y23[0], x0, w23);
        ffma2(y01[1], x1, w01); ffma2(y23[1], x1, w23);
        ffma2(y01[2], x2, w01); ffma2(y23[2], x2, w23);
        ffma2(y01[3], x3, w01); ffma2(y23[3], x3, w23);
    }
    float4 bo = __ldg((const float4*)&ib2[tx * 4]);
#pragma unroll
    for (int r = 0; r < 4; r++) {
        int item = it0 + ty * 4 + r;
        if (item < N_ITEMS) {
            float2 yA = unpack2(y01[r]);
            float2 yB = unpack2(y23[r]);
            ((uint2*)(g_Ih + (size_t)item * D))[tx] =
                make_uint2(f2h2(yA.x + bo.x, yA.y + bo.y),
                           f2h2(yB.x + bo.z, yB.y + bo.w));
        }
    }
}

// ---------------- scores: fp16 tensor-core GEMM (mma.sync m16n8k16) -----------
__global__ __launch_bounds__(256) void k_scores(
        const float* __restrict__ user_bias,
        const float* __restrict__ item_bias,
        const int* __restrict__ users,
        float* __restrict__ out) {
    int lane = threadIdx.x & 31;
    int warp = threadIdx.x >> 5;      // 0..7
    int g = lane >> 2, t = lane & 3;
    int n0 = blockIdx.x * 32;
    int m0 = warp * 32;

    float c[2][4][4] = {};
#pragma unroll
    for (int ks = 0; ks < 4; ks++) {
        unsigned a[2][4], b[4][2];
#pragma unroll
        for (int mt = 0; mt < 2; mt++) {
            const __half* base = g_Uh + (m0 + mt * 16 + g) * D + ks * 16 + 2 * t;
            a[mt][0] = *(const unsigned*)(base);
            a[mt][1] = *(const unsigned*)(base + 8 * D);
            a[mt][2] = *(const unsigned*)(base + 8);
            a[mt][3] = *(const unsigned*)(base + 8 * D + 8);
        }
#pragma unroll
        for (int nt = 0; nt < 4; nt++) {
            const __half* bb = g_Ih + (size_t)(n0 + nt * 8 + g) * D + ks * 16 + 2 * t;
            b[nt][0] = *(const unsigned*)(bb);
            b[nt][1] = *(const unsigned*)(bb + 8);
        }
#pragma unroll
        for (int mt = 0; mt < 2; mt++)
#pragma unroll
            for (int nt = 0; nt < 4; nt++)
                asm volatile(
                    "mma.sync.aligned.m16n8k16.row.col.f32.f16.f16.f32 "
                    "{%0,%1,%2,%3}, {%4,%5,%6,%7}, {%8,%9}, {%0,%1,%2,%3};"
                    : "+f"(c[mt][nt][0]), "+f"(c[mt][nt][1]),
                      "+f"(c[mt][nt][2]), "+f"(c[mt][nt][3])
                    : "r"(a[mt][0]), "r"(a[mt][1]), "r"(a[mt][2]), "r"(a[mt][3]),
                      "r"(b[nt][0]), "r"(b[nt][1]));
    }

#pragma unroll
    for (int mt = 0; mt < 2; mt++) {
        int m = m0 + mt * 16 + g;
        float ub0 = __ldg(&user_bias[__ldg(&users[m])]);
        float ub8 = __ldg(&user_bias[__ldg(&users[m + 8])]);
#pragma unroll
        for (int nt = 0; nt < 4; nt++) {
            int n = n0 + nt * 8 + 2 * t;
            if (n < N_ITEMS) {
                float2 ib = *(const float2*)&item_bias[n];
                float2 r0 = make_float2(c[mt][nt][0] + ub0 + ib.x,
                                        c[mt][nt][1] + ub0 + ib.y);
                float2 r1 = make_float2(c[mt][nt][2] + ub8 + ib.x,
                                        c[mt][nt][3] + ub8 + ib.y);
                __stcs((float2*)&out[(size_t)m * N_ITEMS + n], r0);
                __stcs((float2*)&out[(size_t)(m + 8) * N_ITEMS + n], r1);
            }
        }
    }
}

// ---------------- launch -------------------------------------------------------
extern "C" void kernel_launch(void* const* d_in, const int* in_sizes, int n_in,
                              void* d_out, int out_size) {
    const float* user_emb  = (const float*)d_in[0];
    const float* item_emb  = (const float*)d_in[1];
    const float* user_bias = (const float*)d_in[2];
    const float* item_bias = (const float*)d_in[3];
    const float* pop_emb   = (const float*)d_in[4];
    const float* uW1 = (const float*)d_in[5];
    const float* ub1 = (const float*)d_in[6];
    const float* uW2 = (const float*)d_in[7];
    const float* ub2 = (const float*)d_in[8];
    const float* iW1 = (const float*)d_in[9];
    const float* ib1 = (const float*)d_in[10];
    const float* iW2 = (const float*)d_in[11];
    const float* ib2 = (const float*)d_in[12];
    const float* gW1 = (const float*)d_in[13];
    const float* gb1 = (const float*)d_in[14];
    const float* gW2 = (const float*)d_in[15];
    const float* gb2 = (const float*)d_in[16];
    const float* adj_vals = (const float*)d_in[17];
    const int*   adj_rows = (const int*)d_in[18];
    const int*   adj_cols = (const int*)d_in[19];
    const int*   bins     = (const int*)d_in[20];
    const int*   users    = (const int*)d_in[21];
    float* out = (float*)d_out;

    uint2* e1h; cudaGetSymbolAddress((void**)&e1h, g_e1h);
    uint2* e2h; cudaGetSymbolAddress((void**)&e2h, g_e2h);

    // 1: hist (rank capture) + stage fp16 embeddings
    const int NT4 = N_NODES * D / 4;
    k_histinit<<<(NT4 + 255) / 256, 256>>>(user_emb, item_emb, adj_rows);
    // 2: single-pass decoupled-lookback scan
    int nb = (N_NODES + 1023) / 1024;
    k_scan<<<nb, 1024>>>();
    // 3: rank-based scatter (atomic-free; re-zeroes counts + bstate)
    k_scatter<<<(NNZ + 255) / 256, 256>>>(adj_vals, adj_rows, adj_cols);

    // 4: layer 1 (PROFILED slot) — 2 rows per warp, fp16 gathers (R14 config)
    int spmmBlocks = (N_NODES / 2 * 32 + 255) / 256;   // 9375
    k_spmm<<<spmmBlocks, 256>>>(e2h, e1h);
    // 5: layer 2
    k_spmm<<<spmmBlocks, 256>>>(e1h, e2h);

    // 6: pop precompute + users MLP (merged)
    k_pop_users<<<POPB + BATCH / 2, 64>>>(pop_emb, gW1, iW1,
                                          users, user_emb, uW1, ub1, uW2, ub2);
    // 7: items (FUSED layer-3 SPMM + gate + MLP chain)
    k_items<<<(N_ITEMS + 63) / 64, 256>>>(item_emb, bins, gW1, gb1, gW2, gb2,
                                          iW1, ib1, iW2, ib2);

    // 8: scores (tensor cores)
    k_scores<<<(N_ITEMS + 31) / 32, 256>>>(user_bias, item_bias, users, out);
}